// round 16
// baseline (speedup 1.0000x reference)
#include <cuda_runtime.h>

#define D 64
#define NMAX 100000
#define EMAX 1280000
#define SCAN_BS 1024

__device__ int   g_degi[NMAX];     // out-degree; self-zeroed by gather_post
__device__ int   g_rowptr[NMAX];   // CSR row start (unordered partition of [0,E))
__device__ int   g_cur[NMAX];      // scatter cursors
__device__ int   g_total;          // running total for unordered block prefixes
__device__ int2  g_epack[EMAX];    // {dst node, weight bits} in CSR order

typedef unsigned long long u64;
__device__ __forceinline__ u64 ffma2(u64 a, u64 b, u64 c) {
    u64 d;
    asm("fma.rn.f32x2 %0, %1, %2, %3;" : "=l"(d) : "l"(a), "l"(b), "l"(c));
    return d;
}
__device__ __forceinline__ u64 pack2(float lo, float hi) {
    u64 d;
    asm("mov.b64 %0, {%1, %2};" : "=l"(d) : "f"(lo), "f"(hi));
    return d;
}
__device__ __forceinline__ float lo32(u64 v) { return __uint_as_float((unsigned)v); }
__device__ __forceinline__ float hi32(u64 v) { return __uint_as_float((unsigned)(v >> 32)); }

// ---------------------------------------------------------------------------
// 1. degree histogram over source nodes (g_degi arrives zeroed)
// ---------------------------------------------------------------------------
__global__ void deg_kernel(const int* __restrict__ n1, int E) {
    int e = blockIdx.x * blockDim.x + threadIdx.x;
    if (e < E) atomicAdd(&g_degi[n1[e]], 1);
}

// ---------------------------------------------------------------------------
// 2. single-kernel scan with UNORDERED block prefixes: each block scans its
//    tile locally, then claims a base via atomicAdd(g_total, blocksum).
//    rowptr becomes a valid disjoint partition of [0,E) — gather never needs
//    monotonicity. g_total arrives zeroed (reset by previous gather_post).
// ---------------------------------------------------------------------------
__global__ __launch_bounds__(SCAN_BS) void scan_kernel(int N) {
    __shared__ int wsums[32];
    __shared__ int sh_base;
    int tid = threadIdx.x;
    int lane = tid & 31;
    int w = tid >> 5;
    int i = blockIdx.x * SCAN_BS + tid;
    int v = (i < N) ? g_degi[i] : 0;
    int inc = v;
    #pragma unroll
    for (int off = 1; off < 32; off <<= 1) {
        int t = __shfl_up_sync(0xffffffffu, inc, off);
        if (lane >= off) inc += t;
    }
    if (lane == 31) wsums[w] = inc;
    __syncthreads();
    if (tid < 32) {
        int s = wsums[tid];
        int si = s;
        #pragma unroll
        for (int off = 1; off < 32; off <<= 1) {
            int t = __shfl_up_sync(0xffffffffu, si, off);
            if (lane >= off) si += t;
        }
        wsums[tid] = si - s;                       // exclusive warp base
        if (tid == 31) sh_base = atomicAdd(&g_total, si);   // si = block total
    }
    __syncthreads();
    if (i < N) {
        int r = wsums[w] + inc - v + sh_base;
        g_rowptr[i] = r;
        g_cur[i] = r;
    }
}

// ---------------------------------------------------------------------------
// 3. scatter edges into CSR order with precomputed weights (R14 form)
// ---------------------------------------------------------------------------
__global__ void scatter_kernel(const int* __restrict__ n1,
                               const int* __restrict__ n2,
                               const float* __restrict__ dist,
                               int E) {
    int e = blockIdx.x * blockDim.x + threadIdx.x;
    if (e >= E) return;
    int a = n1[e];
    int c = n2[e];
    float dv = dist[e];
    float w = rsqrtf(__int2float_rn(g_degi[a]) * __int2float_rn(g_degi[c])) * __expf(-dv * dv);
    int pos = atomicAdd(&g_cur[a], 1);
    g_epack[pos] = make_int2(c, __float_as_int(w));
}

// ---------------------------------------------------------------------------
// 4. FUSED gather + post (R14 form) + state reset for next replay:
//    after consuming cnt, zero g_degi[v]; block 0 resets g_total.
// ---------------------------------------------------------------------------
#define FB_ROWS 64
#define WPITCH 33
#define XPITCH 66
__global__ __launch_bounds__(256) void gather_post_kernel(const float* __restrict__ X,
                                                          const float* __restrict__ W,
                                                          const float* __restrict__ b,
                                                          float* __restrict__ out,
                                                          int N) {
    __shared__ u64 Ws2[D * WPITCH];            // 16.9 KB
    __shared__ u64 Xst2[(D / 2) * XPITCH];     // 16.9 KB
    __shared__ float sws[FB_ROWS];

    int tid = threadIdx.x;
    int wid = tid >> 5;
    int l = tid & 31;
    int row0 = blockIdx.x * FB_ROWS;

    if (blockIdx.x == 0 && tid == 0) g_total = 0;   // reset for next replay

    // Load W as u64 pairs (overlaps with gather's memory latency)
    const u64* W2 = reinterpret_cast<const u64*>(W);
    #pragma unroll
    for (int i = tid; i < D * (D / 2); i += 256) {
        int j = i >> 5, kp = i & 31;
        Ws2[j * WPITCH + kp] = W2[i];
    }

    // ---- Phase A: gather 64 nodes, transposed into Xst2 ----
    int grp = tid >> 4;          // lane-group 0..15
    int sub = tid & 15;          // float4 chunk within the 64-float row
    const float4* X4 = reinterpret_cast<const float4*>(X);

    #pragma unroll
    for (int i = 0; i < 4; i++) {
        int r = grp + i * 16;    // row within the block tile
        int v = row0 + r;
        float4 acc = make_float4(0.f, 0.f, 0.f, 0.f);
        float swl = 0.0f;
        if (v < N) {
            int start = g_rowptr[v];
            int cnt = g_degi[v];
            if (sub == 0) g_degi[v] = 0;        // self-zero for next replay
            int j = 0;
            for (; j + 2 <= cnt; j += 2) {
                int2 p0 = g_epack[start + j];
                int2 p1 = g_epack[start + j + 1];
                float4 x0 = X4[(size_t)p0.x * 16 + sub];
                float4 x1 = X4[(size_t)p1.x * 16 + sub];
                float w0 = __int_as_float(p0.y);
                float w1 = __int_as_float(p1.y);
                swl += w0 + w1;
                acc.x = fmaf(w0, x0.x, acc.x);
                acc.y = fmaf(w0, x0.y, acc.y);
                acc.z = fmaf(w0, x0.z, acc.z);
                acc.w = fmaf(w0, x0.w, acc.w);
                acc.x = fmaf(w1, x1.x, acc.x);
                acc.y = fmaf(w1, x1.y, acc.y);
                acc.z = fmaf(w1, x1.z, acc.z);
                acc.w = fmaf(w1, x1.w, acc.w);
            }
            if (j < cnt) {
                int2 p = g_epack[start + j];
                float w = __int_as_float(p.y);
                float4 x = X4[(size_t)p.x * 16 + sub];
                swl += w;
                acc.x = fmaf(w, x.x, acc.x);
                acc.y = fmaf(w, x.y, acc.y);
                acc.z = fmaf(w, x.z, acc.z);
                acc.w = fmaf(w, x.w, acc.w);
            }
        }
        // transpose write: lane sub covers k = 4*sub..4*sub+3 = kp 2*sub, 2*sub+1
        Xst2[(sub * 2 + 0) * XPITCH + r] = pack2(acc.x, acc.y);
        Xst2[(sub * 2 + 1) * XPITCH + r] = pack2(acc.z, acc.w);
        if (sub == 0) sws[r] = swl;
    }
    __syncthreads();

    // ---- Phase B: GEMM + epilogue (proven f32x2 mainloop) ----
    int r0 = wid * 8;
    float bl = b[l], bh = b[l + 32];
    u64 accL[8], accH[8];
    #pragma unroll
    for (int r = 0; r < 8; r++) {
        float s = sws[r0 + r];
        accL[r] = pack2(s * bl, 0.0f);
        accH[r] = pack2(s * bh, 0.0f);
    }

    const u64* wrowL = &Ws2[l * WPITCH];
    const u64* wrowH = &Ws2[(l + 32) * WPITCH];
    #pragma unroll 2
    for (int kp = 0; kp < D / 2; kp++) {
        const u64* xr = &Xst2[kp * XPITCH + r0];
        ulonglong2 x01 = *reinterpret_cast<const ulonglong2*>(xr);
        ulonglong2 x23 = *reinterpret_cast<const ulonglong2*>(xr + 2);
        ulonglong2 x45 = *reinterpret_cast<const ulonglong2*>(xr + 4);
        ulonglong2 x67 = *reinterpret_cast<const ulonglong2*>(xr + 6);
        u64 wl = wrowL[kp];
        u64 wh = wrowH[kp];
        accL[0] = ffma2(x01.x, wl, accL[0]);  accH[0] = ffma2(x01.x, wh, accH[0]);
        accL[1] = ffma2(x01.y, wl, accL[1]);  accH[1] = ffma2(x01.y, wh, accH[1]);
        accL[2] = ffma2(x23.x, wl, accL[2]);  accH[2] = ffma2(x23.x, wh, accH[2]);
        accL[3] = ffma2(x23.y, wl, accL[3]);  accH[3] = ffma2(x23.y, wh, accH[3]);
        accL[4] = ffma2(x45.x, wl, accL[4]);  accH[4] = ffma2(x45.x, wh, accH[4]);
        accL[5] = ffma2(x45.y, wl, accL[5]);  accH[5] = ffma2(x45.y, wh, accH[5]);
        accL[6] = ffma2(x67.x, wl, accL[6]);  accH[6] = ffma2(x67.x, wh, accH[6]);
        accL[7] = ffma2(x67.y, wl, accL[7]);  accH[7] = ffma2(x67.y, wh, accH[7]);
    }

    #pragma unroll
    for (int r = 0; r < 8; r++) {
        float vL = lo32(accL[r]) + hi32(accL[r]);
        float vH = lo32(accH[r]) + hi32(accH[r]);
        vL = (vL >= 0.0f) ? vL : 0.01f * vL;
        vH = (vH >= 0.0f) ? vH : 0.01f * vH;
        float ss = vL * vL + vH * vH;
        #pragma unroll
        for (int o = 16; o > 0; o >>= 1) ss += __shfl_xor_sync(0xffffffffu, ss, o);
        int row = row0 + r0 + r;
        if (row < N) {
            float inv = 1.0f / fmaxf(sqrtf(ss), 1e-12f);
            out[(size_t)row * D + l]      = vL * inv;
            out[(size_t)row * D + l + 32] = vH * inv;
        }
    }
}

// ---------------------------------------------------------------------------
// Launch — 4 kernels total
// ---------------------------------------------------------------------------
extern "C" void kernel_launch(void* const* d_in, const int* in_sizes, int n_in,
                              void* d_out, int out_size) {
    const float* poi  = (const float*)d_in[0];
    const int*   eidx = (const int*)d_in[1];
    const float* dist = (const float*)d_in[2];
    const float* W    = (const float*)d_in[3];
    const float* b    = (const float*)d_in[4];
    float* out = (float*)d_out;

    int N = in_sizes[0] / D;
    int E = in_sizes[1] / 2;
    const int* n1 = eidx;
    const int* n2 = eidx + E;
    int nb = (N + SCAN_BS - 1) / SCAN_BS;

    deg_kernel<<<(E + 255) / 256, 256>>>(n1, E);
    scan_kernel<<<nb, SCAN_BS>>>(N);
    scatter_kernel<<<(E + 255) / 256, 256>>>(n1, n2, dist, E);
    {
        int blocks = (N + FB_ROWS - 1) / FB_ROWS;
        gather_post_kernel<<<blocks, 256>>>(poi, W, b, out, N);
    }
}

// round 17
// speedup vs baseline: 1.5492x; 1.5492x over previous
#include <cuda_runtime.h>

#define D 64
#define NMAX 100000
#define EMAX 1280000
#define SCAN_BS 1024

__device__ int   g_degi[NMAX];     // out-degree (int)
__device__ int   g_rowptr[NMAX];   // CSR row start
__device__ int   g_cur[NMAX];      // scatter cursors
__device__ int   g_bsums[128];     // scan block sums
__device__ int2  g_epack[EMAX];    // {dst node, weight bits} in CSR order

typedef unsigned long long u64;
__device__ __forceinline__ u64 ffma2(u64 a, u64 b, u64 c) {
    u64 d;
    asm("fma.rn.f32x2 %0, %1, %2, %3;" : "=l"(d) : "l"(a), "l"(b), "l"(c));
    return d;
}
__device__ __forceinline__ u64 pack2(float lo, float hi) {
    u64 d;
    asm("mov.b64 %0, {%1, %2};" : "=l"(d) : "f"(lo), "f"(hi));
    return d;
}
__device__ __forceinline__ float lo32(u64 v) { return __uint_as_float((unsigned)v); }
__device__ __forceinline__ float hi32(u64 v) { return __uint_as_float((unsigned)(v >> 32)); }

// ---------------------------------------------------------------------------
// 1. zero degree counters (no PDL sync needed: reads only harness inputs)
// ---------------------------------------------------------------------------
__global__ void zero_deg_kernel(int N) {
    int i = blockIdx.x * blockDim.x + threadIdx.x;
    if (i < N) g_degi[i] = 0;
}

// ---------------------------------------------------------------------------
// 2. degree histogram (depends on zero_deg)
// ---------------------------------------------------------------------------
__global__ void deg_kernel(const int* __restrict__ n1, int E) {
    cudaGridDependencySynchronize();
    int e = blockIdx.x * blockDim.x + threadIdx.x;
    if (e < E) atomicAdd(&g_degi[n1[e]], 1);
}

// ---------------------------------------------------------------------------
// 3. per-block scan of g_degi via warp shuffles (depends on deg)
// ---------------------------------------------------------------------------
__global__ void scan1_kernel(int N) {
    __shared__ int wsums[32];
    cudaGridDependencySynchronize();
    int tid = threadIdx.x;
    int lane = tid & 31;
    int w = tid >> 5;
    int i = blockIdx.x * SCAN_BS + tid;
    int v = (i < N) ? g_degi[i] : 0;
    int inc = v;
    #pragma unroll
    for (int off = 1; off < 32; off <<= 1) {
        int t = __shfl_up_sync(0xffffffffu, inc, off);
        if (lane >= off) inc += t;
    }
    if (lane == 31) wsums[w] = inc;
    __syncthreads();
    if (tid < 32) {
        int s = wsums[tid];
        int si = s;
        #pragma unroll
        for (int off = 1; off < 32; off <<= 1) {
            int t = __shfl_up_sync(0xffffffffu, si, off);
            if (lane >= off) si += t;
        }
        wsums[tid] = si - s;   // exclusive warp base
    }
    __syncthreads();
    if (i < N) g_rowptr[i] = wsums[w] + inc - v;      // exclusive within block
    if (tid == SCAN_BS - 1) g_bsums[blockIdx.x] = wsums[31] + inc;
}

// ---------------------------------------------------------------------------
// 4. fused block-sum scan + apply (depends on scan1)
// ---------------------------------------------------------------------------
__global__ void scan3_kernel(int N, int nb) {
    __shared__ int wsum[4];
    __shared__ int pref;
    cudaGridDependencySynchronize();
    int tid = threadIdx.x;
    if (tid < 128) {
        int lane = tid & 31;
        int w = tid >> 5;
        int v = (tid < nb) ? g_bsums[tid] : 0;
        int inc = v;
        #pragma unroll
        for (int off = 1; off < 32; off <<= 1) {
            int t = __shfl_up_sync(0xffffffffu, inc, off);
            if (lane >= off) inc += t;
        }
        if (lane == 31) wsum[w] = inc;
    }
    __syncthreads();
    if (tid < 128) {
        int lane = tid & 31;
        int w = tid >> 5;
        int v = (tid < nb) ? g_bsums[tid] : 0;
        int inc = v;
        #pragma unroll
        for (int off = 1; off < 32; off <<= 1) {
            int t = __shfl_up_sync(0xffffffffu, inc, off);
            if (lane >= off) inc += t;
        }
        int base = 0;
        #pragma unroll
        for (int k = 0; k < 4; k++) base += (k < w) ? wsum[k] : 0;
        if (tid == blockIdx.x) pref = base + inc - v;   // exclusive prefix
    }
    __syncthreads();
    int i = blockIdx.x * SCAN_BS + tid;
    if (i < N) {
        int r = g_rowptr[i] + pref;
        g_rowptr[i] = r;
        g_cur[i] = r;
    }
}

// ---------------------------------------------------------------------------
// 5. scatter edges into CSR order (depends on scan3)
// ---------------------------------------------------------------------------
__global__ void scatter_kernel(const int* __restrict__ n1,
                               const int* __restrict__ n2,
                               const float* __restrict__ dist,
                               int E) {
    cudaGridDependencySynchronize();
    int e = blockIdx.x * blockDim.x + threadIdx.x;
    if (e >= E) return;
    int a = n1[e];
    int c = n2[e];
    float dv = dist[e];
    float w = rsqrtf(__int2float_rn(g_degi[a]) * __int2float_rn(g_degi[c])) * __expf(-dv * dv);
    int pos = atomicAdd(&g_cur[a], 1);
    g_epack[pos] = make_int2(c, __float_as_int(w));
}

// ---------------------------------------------------------------------------
// 6. FUSED gather + post (R14 form, depends on scatter)
// ---------------------------------------------------------------------------
#define FB_ROWS 64
#define WPITCH 33
#define XPITCH 66
__global__ __launch_bounds__(256) void gather_post_kernel(const float* __restrict__ X,
                                                          const float* __restrict__ W,
                                                          const float* __restrict__ b,
                                                          float* __restrict__ out,
                                                          int N) {
    __shared__ u64 Ws2[D * WPITCH];            // 16.9 KB
    __shared__ u64 Xst2[(D / 2) * XPITCH];     // 16.9 KB
    __shared__ float sws[FB_ROWS];

    cudaGridDependencySynchronize();

    int tid = threadIdx.x;
    int wid = tid >> 5;
    int l = tid & 31;
    int row0 = blockIdx.x * FB_ROWS;

    // Load W as u64 pairs (overlaps with gather's memory latency)
    const u64* W2 = reinterpret_cast<const u64*>(W);
    #pragma unroll
    for (int i = tid; i < D * (D / 2); i += 256) {
        int j = i >> 5, kp = i & 31;
        Ws2[j * WPITCH + kp] = W2[i];
    }

    // ---- Phase A: gather 64 nodes, transposed into Xst2 ----
    int grp = tid >> 4;          // lane-group 0..15
    int sub = tid & 15;          // float4 chunk within the 64-float row
    const float4* X4 = reinterpret_cast<const float4*>(X);

    #pragma unroll
    for (int i = 0; i < 4; i++) {
        int r = grp + i * 16;    // row within the block tile
        int v = row0 + r;
        float4 acc = make_float4(0.f, 0.f, 0.f, 0.f);
        float swl = 0.0f;
        if (v < N) {
            int start = g_rowptr[v];
            int cnt = g_degi[v];
            int j = 0;
            for (; j + 2 <= cnt; j += 2) {
                int2 p0 = g_epack[start + j];
                int2 p1 = g_epack[start + j + 1];
                float4 x0 = X4[(size_t)p0.x * 16 + sub];
                float4 x1 = X4[(size_t)p1.x * 16 + sub];
                float w0 = __int_as_float(p0.y);
                float w1 = __int_as_float(p1.y);
                swl += w0 + w1;
                acc.x = fmaf(w0, x0.x, acc.x);
                acc.y = fmaf(w0, x0.y, acc.y);
                acc.z = fmaf(w0, x0.z, acc.z);
                acc.w = fmaf(w0, x0.w, acc.w);
                acc.x = fmaf(w1, x1.x, acc.x);
                acc.y = fmaf(w1, x1.y, acc.y);
                acc.z = fmaf(w1, x1.z, acc.z);
                acc.w = fmaf(w1, x1.w, acc.w);
            }
            if (j < cnt) {
                int2 p = g_epack[start + j];
                float w = __int_as_float(p.y);
                float4 x = X4[(size_t)p.x * 16 + sub];
                swl += w;
                acc.x = fmaf(w, x.x, acc.x);
                acc.y = fmaf(w, x.y, acc.y);
                acc.z = fmaf(w, x.z, acc.z);
                acc.w = fmaf(w, x.w, acc.w);
            }
        }
        // transpose write: lane sub covers k = 4*sub..4*sub+3 = kp 2*sub, 2*sub+1
        Xst2[(sub * 2 + 0) * XPITCH + r] = pack2(acc.x, acc.y);
        Xst2[(sub * 2 + 1) * XPITCH + r] = pack2(acc.z, acc.w);
        if (sub == 0) sws[r] = swl;
    }
    __syncthreads();

    // ---- Phase B: GEMM + epilogue (proven f32x2 mainloop) ----
    int r0 = wid * 8;
    float bl = b[l], bh = b[l + 32];
    u64 accL[8], accH[8];
    #pragma unroll
    for (int r = 0; r < 8; r++) {
        float s = sws[r0 + r];
        accL[r] = pack2(s * bl, 0.0f);
        accH[r] = pack2(s * bh, 0.0f);
    }

    const u64* wrowL = &Ws2[l * WPITCH];
    const u64* wrowH = &Ws2[(l + 32) * WPITCH];
    #pragma unroll 2
    for (int kp = 0; kp < D / 2; kp++) {
        const u64* xr = &Xst2[kp * XPITCH + r0];
        ulonglong2 x01 = *reinterpret_cast<const ulonglong2*>(xr);
        ulonglong2 x23 = *reinterpret_cast<const ulonglong2*>(xr + 2);
        ulonglong2 x45 = *reinterpret_cast<const ulonglong2*>(xr + 4);
        ulonglong2 x67 = *reinterpret_cast<const ulonglong2*>(xr + 6);
        u64 wl = wrowL[kp];
        u64 wh = wrowH[kp];
        accL[0] = ffma2(x01.x, wl, accL[0]);  accH[0] = ffma2(x01.x, wh, accH[0]);
        accL[1] = ffma2(x01.y, wl, accL[1]);  accH[1] = ffma2(x01.y, wh, accH[1]);
        accL[2] = ffma2(x23.x, wl, accL[2]);  accH[2] = ffma2(x23.x, wh, accH[2]);
        accL[3] = ffma2(x23.y, wl, accL[3]);  accH[3] = ffma2(x23.y, wh, accH[3]);
        accL[4] = ffma2(x45.x, wl, accL[4]);  accH[4] = ffma2(x45.x, wh, accH[4]);
        accL[5] = ffma2(x45.y, wl, accL[5]);  accH[5] = ffma2(x45.y, wh, accH[5]);
        accL[6] = ffma2(x67.x, wl, accL[6]);  accH[6] = ffma2(x67.x, wh, accH[6]);
        accL[7] = ffma2(x67.y, wl, accL[7]);  accH[7] = ffma2(x67.y, wh, accH[7]);
    }

    #pragma unroll
    for (int r = 0; r < 8; r++) {
        float vL = lo32(accL[r]) + hi32(accL[r]);
        float vH = lo32(accH[r]) + hi32(accH[r]);
        vL = (vL >= 0.0f) ? vL : 0.01f * vL;
        vH = (vH >= 0.0f) ? vH : 0.01f * vH;
        float ss = vL * vL + vH * vH;
        #pragma unroll
        for (int o = 16; o > 0; o >>= 1) ss += __shfl_xor_sync(0xffffffffu, ss, o);
        int row = row0 + r0 + r;
        if (row < N) {
            float inv = 1.0f / fmaxf(sqrtf(ss), 1e-12f);
            out[(size_t)row * D + l]      = vL * inv;
            out[(size_t)row * D + l + 32] = vH * inv;
        }
    }
}

// ---------------------------------------------------------------------------
// Launch — 6 kernels, PDL-chained (each overlaps predecessor's drain)
// ---------------------------------------------------------------------------
template <typename F, typename... Args>
static void launch_pdl(F func, dim3 grid, dim3 block, Args... args) {
    cudaLaunchConfig_t cfg = {};
    cfg.gridDim = grid;
    cfg.blockDim = block;
    cudaLaunchAttribute attr[1];
    attr[0].id = cudaLaunchAttributeProgrammaticStreamSerialization;
    attr[0].val.programmaticStreamSerializationAllowed = 1;
    cfg.attrs = attr;
    cfg.numAttrs = 1;
    cudaLaunchKernelEx(&cfg, func, args...);
}

extern "C" void kernel_launch(void* const* d_in, const int* in_sizes, int n_in,
                              void* d_out, int out_size) {
    const float* poi  = (const float*)d_in[0];
    const int*   eidx = (const int*)d_in[1];
    const float* dist = (const float*)d_in[2];
    const float* W    = (const float*)d_in[3];
    const float* b    = (const float*)d_in[4];
    float* out = (float*)d_out;

    int N = in_sizes[0] / D;
    int E = in_sizes[1] / 2;
    const int* n1 = eidx;
    const int* n2 = eidx + E;
    int nb = (N + SCAN_BS - 1) / SCAN_BS;

    zero_deg_kernel<<<(N + 255) / 256, 256>>>(N);
    launch_pdl(deg_kernel, dim3((E + 255) / 256), dim3(256), n1, E);
    launch_pdl(scan1_kernel, dim3(nb), dim3(SCAN_BS), N);
    launch_pdl(scan3_kernel, dim3(nb), dim3(SCAN_BS), N, nb);
    launch_pdl(scatter_kernel, dim3((E + 255) / 256), dim3(256), n1, n2, dist, E);
    launch_pdl(gather_post_kernel, dim3((N + FB_ROWS - 1) / FB_ROWS), dim3(256),
               poi, W, b, out, N);
}